// round 2
// baseline (speedup 1.0000x reference)
#include <cuda_runtime.h>

// ---------------- scratch (no cudaMalloc allowed) ----------------
__device__ float g_h1[256 * 1024 * 8];   // LSTM1 outputs, [B][S][8], 8MB

// ---------------- fast activations ----------------
__device__ __forceinline__ float fast_rcp(float x) {
    float r; asm("rcp.approx.ftz.f32 %0, %1;" : "=f"(r) : "f"(x)); return r;
}
__device__ __forceinline__ float fast_ex2(float x) {
    float r; asm("ex2.approx.ftz.f32 %0, %1;" : "=f"(r) : "f"(x)); return r;
}
// sigmoid(x) = 1 / (1 + exp(-x)) = 1 / (1 + 2^(-x*log2e))
__device__ __forceinline__ float sigf(float x) {
    return fast_rcp(1.0f + fast_ex2(-1.4426950408889634f * x));
}
// tanh(x) = 2*sigmoid(2x) - 1
__device__ __forceinline__ float tanh_(float x) {
    return fmaf(2.0f, sigf(2.0f * x), -1.0f);
}
__device__ __forceinline__ float dot4(float4 w, float4 v, float a) {
    a = fmaf(w.x, v.x, a); a = fmaf(w.y, v.y, a);
    a = fmaf(w.z, v.z, a); a = fmaf(w.w, v.w, a);
    return a;
}

// =================================================================
// Kernel 1: LSTM1. One thread per (b,s) sequence: 16 steps, input=1, H=8.
// =================================================================
__global__ __launch_bounds__(256) void lstm1_kernel(
    const float* __restrict__ x,
    const float* __restrict__ W_ih1, const float* __restrict__ W_hh1,
    const float* __restrict__ b_ih1, const float* __restrict__ b_hh1)
{
    __shared__ float sw_ih[32];
    __shared__ float sw_hh[32][8];
    __shared__ float sbias[32];
    int tid = threadIdx.x;
    if (tid < 32) { sw_ih[tid] = W_ih1[tid]; sbias[tid] = b_ih1[tid] + b_hh1[tid]; }
    if (tid < 256) sw_hh[tid >> 3][tid & 7] = W_hh1[tid];
    __syncthreads();

    long n = (long)blockIdx.x * 256 + tid;   // 0 .. 262143
    const float4* xp = (const float4*)(x + n * 16);
    float4 xq[4];
    xq[0] = xp[0]; xq[1] = xp[1]; xq[2] = xp[2]; xq[3] = xp[3];
    float xv[16];
#pragma unroll
    for (int i = 0; i < 4; i++) {
        xv[4 * i + 0] = xq[i].x; xv[4 * i + 1] = xq[i].y;
        xv[4 * i + 2] = xq[i].z; xv[4 * i + 3] = xq[i].w;
    }

    float h[8], c[8];
#pragma unroll
    for (int d = 0; d < 8; d++) { h[d] = 0.f; c[d] = 0.f; }

#pragma unroll
    for (int t = 0; t < 16; t++) {
        float xt = xv[t];
        float hn[8];
#pragma unroll
        for (int d = 0; d < 8; d++) {
            float gi = fmaf(sw_ih[d],      xt, sbias[d]);
            float gf = fmaf(sw_ih[8 + d],  xt, sbias[8 + d]);
            float gg = fmaf(sw_ih[16 + d], xt, sbias[16 + d]);
            float go = fmaf(sw_ih[24 + d], xt, sbias[24 + d]);
#pragma unroll
            for (int e = 0; e < 8; e++) {
                float he = h[e];
                gi = fmaf(sw_hh[d][e],      he, gi);
                gf = fmaf(sw_hh[8 + d][e],  he, gf);
                gg = fmaf(sw_hh[16 + d][e], he, gg);
                go = fmaf(sw_hh[24 + d][e], he, go);
            }
            c[d]  = sigf(gf) * c[d] + sigf(gi) * tanh_(gg);
            hn[d] = sigf(go) * tanh_(c[d]);
        }
#pragma unroll
        for (int d = 0; d < 8; d++) h[d] = hn[d];
    }

    float4* o = (float4*)(g_h1 + n * 8);
    o[0] = make_float4(h[0], h[1], h[2], h[3]);
    o[1] = make_float4(h[4], h[5], h[6], h[7]);
}

// =================================================================
// Kernel 2: LSTM2 (persistent, 128 CTAs x 512 threads, 2 batches/CTA)
// + final dense 128->64->1 epilogue.
// Thread t owns gate-row t. W row (len 136 = 8 ih + 128 hh) split:
//   k in [0,88)  -> smem Ws[512][92]  (stride 92 words: conflict-free LDS.128)
//   k in [88,136)-> 48 registers per thread
// vec[b][144]: [0..8) = x_t, [8..136) = h. Single buffer, 2 syncs/step.
// =================================================================
#define WSTR 92
#define VSTR 144
// floats: Ws 512*92 + vec 2*144 + gstage 512*2 + red 8
#define SM_FLOATS (512 * WSTR + 2 * VSTR + 512 * 2 + 8)
#define SM_BYTES  (SM_FLOATS * 4)

__global__ void __launch_bounds__(512, 1) lstm2_kernel(
    const float* __restrict__ W_ih2, const float* __restrict__ W_hh2,
    const float* __restrict__ b_ih2, const float* __restrict__ b_hh2,
    const float* __restrict__ W1, const float* __restrict__ b1,
    const float* __restrict__ W2, const float* __restrict__ b2,
    float* __restrict__ out)
{
    extern __shared__ float sm[];
    float* Ws  = sm;                         // [512][92]
    float* vec = sm + 512 * WSTR;            // [2][144]
    float* gst = vec + 2 * VSTR;             // [512][2]
    float* red = gst + 512 * 2;              // [8]

    const int t  = threadIdx.x;
    const int b0 = blockIdx.x * 2;           // 2 batches per CTA

    // ---- load W rows (k 0..87) into smem ----
    for (int idx = t; idx < 512 * 88; idx += 512) {
        int j = idx / 88, kk = idx - j * 88;
        float w = (kk < 8) ? W_ih2[j * 8 + kk] : W_hh2[j * 128 + (kk - 8)];
        Ws[j * WSTR + kk] = w;
    }
    // ---- load W tail (k 88..135 == hh cols 80..127) into registers ----
    float rW[48];
    {
        const float4* wr = (const float4*)(W_hh2 + t * 128 + 80);
#pragma unroll
        for (int q = 0; q < 12; q++) {
            float4 v = wr[q];
            rW[4 * q + 0] = v.x; rW[4 * q + 1] = v.y;
            rW[4 * q + 2] = v.z; rW[4 * q + 3] = v.w;
        }
    }
    const float bias = b_ih2[t] + b_hh2[t];

    // ---- init vec (h=0) and stage x_0 ----
    if (t < 2 * VSTR) vec[t] = 0.f;
    __syncthreads();
    if (t < 16) {
        int b = t >> 3, k = t & 7;
        vec[b * VSTR + k] = g_h1[((long)(b0 + b) * 1024 + 0) * 8 + k];
    }
    float c = 0.f;     // cell state (threads t<256: d = t&127, b = t>>7)
    float xr = 0.f;    // x prefetch register (threads 256..271)
    if (t >= 256 && t < 272) {
        int u = t - 256, b = u >> 3, k = u & 7;
        xr = g_h1[((long)(b0 + b) * 1024 + 1) * 8 + k];
    }
    __syncthreads();

    for (int step = 0; step < 1024; step++) {
        // ---- phase A: gates (all 512 threads, one row each, 2 batches) ----
        float a0 = bias, a1 = bias;
        const float4* w4 = (const float4*)(Ws + t * WSTR);
        const float4* v0 = (const float4*)(vec);
        const float4* v1 = (const float4*)(vec + VSTR);
#pragma unroll
        for (int q = 0; q < 22; q++) {
            float4 w = w4[q];
            a0 = dot4(w, v0[q], a0);
            a1 = dot4(w, v1[q], a1);
        }
#pragma unroll
        for (int q = 0; q < 12; q++) {
            float4 w = make_float4(rW[4 * q], rW[4 * q + 1], rW[4 * q + 2], rW[4 * q + 3]);
            a0 = dot4(w, v0[22 + q], a0);
            a1 = dot4(w, v1[22 + q], a1);
        }
        ((float2*)gst)[t] = make_float2(a0, a1);
        __syncthreads();

        // ---- phase B: activations + h/x staging ----
        if (t < 256) {
            int d = t & 127, b = t >> 7;
            float gi = gst[(d)       * 2 + b];
            float gf = gst[(128 + d) * 2 + b];
            float gg = gst[(256 + d) * 2 + b];
            float go = gst[(384 + d) * 2 + b];
            c = sigf(gf) * c + sigf(gi) * tanh_(gg);
            float h = sigf(go) * tanh_(c);
            vec[b * VSTR + 8 + d] = h;
        } else if (t < 272) {
            int u = t - 256, b = u >> 3, k = u & 7;
            vec[b * VSTR + k] = xr;                    // x_{step+1}
            int nt = step + 2;
            if (nt < 1024)
                xr = g_h1[((long)(b0 + b) * 1024 + nt) * 8 + k];
        }
        __syncthreads();
    }

    // ---- epilogue: out[b] = (h @ W1^T + b1) @ W2^T + b2 ----
    if (t < 128) {
        int b = t >> 6, j = t & 63;
        const float4* hv4 = (const float4*)(vec + b * VSTR + 8);
        const float4* w1  = (const float4*)(W1 + j * 128);
        float m = b1[j];
#pragma unroll
        for (int q = 0; q < 32; q++) m = dot4(w1[q], hv4[q], m);
        float p = m * W2[j];
#pragma unroll
        for (int off = 16; off; off >>= 1)
            p += __shfl_xor_sync(0xffffffff, p, off);
        if ((t & 31) == 0) red[t >> 5] = p;
    }
    __syncthreads();
    if (t < 2)
        out[b0 + t] = red[t * 2] + red[t * 2 + 1] + b2[0];
}

// =================================================================
extern "C" void kernel_launch(void* const* d_in, const int* in_sizes, int n_in,
                              void* d_out, int out_size) {
    const float* x     = (const float*)d_in[0];
    // d_in[1] = data (unused)
    const float* W_ih1 = (const float*)d_in[2];
    const float* W_hh1 = (const float*)d_in[3];
    const float* b_ih1 = (const float*)d_in[4];
    const float* b_hh1 = (const float*)d_in[5];
    const float* W_ih2 = (const float*)d_in[6];
    const float* W_hh2 = (const float*)d_in[7];
    const float* b_ih2 = (const float*)d_in[8];
    const float* b_hh2 = (const float*)d_in[9];
    const float* W1    = (const float*)d_in[10];
    const float* b1    = (const float*)d_in[11];
    const float* W2    = (const float*)d_in[12];
    const float* b2    = (const float*)d_in[13];
    float* out = (float*)d_out;

    lstm1_kernel<<<1024, 256>>>(x, W_ih1, W_hh1, b_ih1, b_hh1);

    cudaFuncSetAttribute(lstm2_kernel,
                         cudaFuncAttributeMaxDynamicSharedMemorySize, SM_BYTES);
    lstm2_kernel<<<128, 512, SM_BYTES>>>(W_ih2, W_hh2, b_ih2, b_hh2,
                                         W1, b1, W2, b2, out);
}

// round 3
// speedup vs baseline: 1.0127x; 1.0127x over previous
#include <cuda_runtime.h>

// ---------------- scratch (no cudaMalloc allowed) ----------------
__device__ float g_h1[256 * 1024 * 8];   // LSTM1 outputs, [B][S][8], 8MB

// ---------------- fast activations ----------------
__device__ __forceinline__ float fast_rcp(float x) {
    float r; asm("rcp.approx.ftz.f32 %0, %1;" : "=f"(r) : "f"(x)); return r;
}
__device__ __forceinline__ float fast_ex2(float x) {
    float r; asm("ex2.approx.ftz.f32 %0, %1;" : "=f"(r) : "f"(x)); return r;
}
// sigmoid(x) = 1 / (1 + 2^(-x*log2e))
__device__ __forceinline__ float sigf(float x) {
    return fast_rcp(1.0f + fast_ex2(-1.4426950408889634f * x));
}
// tanh(x) = 2*sigmoid(2x) - 1
__device__ __forceinline__ float tanh_(float x) {
    return fmaf(2.0f, sigf(2.0f * x), -1.0f);
}
__device__ __forceinline__ float dot4(float4 w, float4 v, float a) {
    a = fmaf(w.x, v.x, a); a = fmaf(w.y, v.y, a);
    a = fmaf(w.z, v.z, a); a = fmaf(w.w, v.w, a);
    return a;
}

// =================================================================
// Kernel 1: LSTM1. One thread per (b,s) sequence: 16 steps, input=1, H=8.
// =================================================================
__global__ __launch_bounds__(256) void lstm1_kernel(
    const float* __restrict__ x,
    const float* __restrict__ W_ih1, const float* __restrict__ W_hh1,
    const float* __restrict__ b_ih1, const float* __restrict__ b_hh1)
{
    __shared__ float sw_ih[32];
    __shared__ float sw_hh[32][8];
    __shared__ float sbias[32];
    int tid = threadIdx.x;
    if (tid < 32) { sw_ih[tid] = W_ih1[tid]; sbias[tid] = b_ih1[tid] + b_hh1[tid]; }
    if (tid < 256) sw_hh[tid >> 3][tid & 7] = W_hh1[tid];
    __syncthreads();

    long n = (long)blockIdx.x * 256 + tid;   // 0 .. 262143
    const float4* xp = (const float4*)(x + n * 16);
    float4 xq[4];
    xq[0] = xp[0]; xq[1] = xp[1]; xq[2] = xp[2]; xq[3] = xp[3];
    float xv[16];
#pragma unroll
    for (int i = 0; i < 4; i++) {
        xv[4 * i + 0] = xq[i].x; xv[4 * i + 1] = xq[i].y;
        xv[4 * i + 2] = xq[i].z; xv[4 * i + 3] = xq[i].w;
    }

    float h[8], c[8];
#pragma unroll
    for (int d = 0; d < 8; d++) { h[d] = 0.f; c[d] = 0.f; }

#pragma unroll
    for (int t = 0; t < 16; t++) {
        float xt = xv[t];
        float hn[8];
#pragma unroll
        for (int d = 0; d < 8; d++) {
            float gi = fmaf(sw_ih[d],      xt, sbias[d]);
            float gf = fmaf(sw_ih[8 + d],  xt, sbias[8 + d]);
            float gg = fmaf(sw_ih[16 + d], xt, sbias[16 + d]);
            float go = fmaf(sw_ih[24 + d], xt, sbias[24 + d]);
#pragma unroll
            for (int e = 0; e < 8; e++) {
                float he = h[e];
                gi = fmaf(sw_hh[d][e],      he, gi);
                gf = fmaf(sw_hh[8 + d][e],  he, gf);
                gg = fmaf(sw_hh[16 + d][e], he, gg);
                go = fmaf(sw_hh[24 + d][e], he, go);
            }
            c[d]  = sigf(gf) * c[d] + sigf(gi) * tanh_(gg);
            hn[d] = sigf(go) * tanh_(c[d]);
        }
#pragma unroll
        for (int d = 0; d < 8; d++) h[d] = hn[d];
    }

    float4* o = (float4*)(g_h1 + n * 8);
    o[0] = make_float4(h[0], h[1], h[2], h[3]);
    o[1] = make_float4(h[4], h[5], h[6], h[7]);
}

// =================================================================
// Kernel 2: LSTM2, persistent, 128 CTAs x 1024 threads, 2 batches/CTA.
// Split-K: thread t owns (row j = t&511, half = t>>9).
//   half h covers k in [68h, 68h+68) of the 136-length row
//     (k 0..7 = W_ih cols, k 8..135 = W_hh cols 0..127)
//   first 44 k-values of each half live in smem Ws[512][92]
//     (cols [0,44) = half0, cols [44,88) = half1; stride 92: conflict-free)
//   last 24 k-values of each half live in 24 registers.
// vec[b][144]: [0..8) = x_t, [8..136) = h.
// Partial gate sums exchanged via gst[512] float4 = {a0h0,a1h0,a0h1,a1h1}.
// =================================================================
#define WSTR 92
#define VSTR 144
// floats: Ws 512*92 + vec 2*144 + gst 512*4 + red 8
#define SM_FLOATS (512 * WSTR + 2 * VSTR + 512 * 4 + 8)
#define SM_BYTES  (SM_FLOATS * 4)

__global__ void __launch_bounds__(1024, 1) lstm2_kernel(
    const float* __restrict__ W_ih2, const float* __restrict__ W_hh2,
    const float* __restrict__ b_ih2, const float* __restrict__ b_hh2,
    const float* __restrict__ W1, const float* __restrict__ b1,
    const float* __restrict__ W2, const float* __restrict__ b2,
    float* __restrict__ out)
{
    extern __shared__ float sm[];
    float* Ws  = sm;                         // [512][92]
    float* vec = sm + 512 * WSTR;            // [2][144]
    float* gst = vec + 2 * VSTR;             // [512][4]
    float* red = gst + 512 * 4;              // [8]

    const int t    = threadIdx.x;
    const int j    = t & 511;                // gate row
    const int half = t >> 9;                 // k-half
    const int b0   = blockIdx.x * 2;         // 2 batches per CTA

    // ---- load smem-resident weights: per row, half0 k[0,44) and half1 k[68,112) ----
    for (int idx = t; idx < 512 * 88; idx += 1024) {
        int jj = idx / 88, kk = idx - jj * 88;
        int hf = (kk < 44) ? 0 : 1;
        int kglob = hf * 68 + (kk - 44 * hf);   // global k in [0,136)
        float w = (kglob < 8) ? W_ih2[jj * 8 + kglob]
                              : W_hh2[jj * 128 + (kglob - 8)];
        Ws[jj * WSTR + kk] = w;
    }
    // ---- register weights: this thread's k in [68*half+44, 68*half+68) ----
    // global k maps to hh cols (k-8): half0 -> hh 36..59, half1 -> hh 104..127
    float rW[24];
    {
        const float4* wr = (const float4*)(W_hh2 + j * 128 + 36 + half * 68);
#pragma unroll
        for (int q = 0; q < 6; q++) {
            float4 v = wr[q];
            rW[4 * q + 0] = v.x; rW[4 * q + 1] = v.y;
            rW[4 * q + 2] = v.z; rW[4 * q + 3] = v.w;
        }
    }
    const float bias = half ? 0.f : (b_ih2[j] + b_hh2[j]);

    // ---- init vec (h=0) and stage x_0 ----
    if (t < 2 * VSTR) vec[t] = 0.f;
    __syncthreads();
    if (t < 16) {
        int b = t >> 3, k = t & 7;
        vec[b * VSTR + k] = g_h1[((long)(b0 + b) * 1024 + 0) * 8 + k];
    }
    float c = 0.f;     // cell state (threads t<256: d = t&127, b = t>>7)
    float xr = 0.f;    // x prefetch register (threads 256..271)
    if (t >= 256 && t < 272) {
        int u = t - 256, b = u >> 3, k = u & 7;
        xr = g_h1[((long)(b0 + b) * 1024 + 1) * 8 + k];
    }
    __syncthreads();

    const float4* w4  = (const float4*)(Ws + j * WSTR + half * 44);  // 11 float4
    const float4* vv0 = (const float4*)(vec + half * 68);            // 17 float4 window
    const float4* vv1 = (const float4*)(vec + VSTR + half * 68);

    for (int step = 0; step < 1024; step++) {
        // ---- phase A: half-row dot products, 2 batches ----
        float a0 = bias, a1 = bias;
#pragma unroll
        for (int q = 0; q < 11; q++) {
            float4 w = w4[q];
            a0 = dot4(w, vv0[q], a0);
            a1 = dot4(w, vv1[q], a1);
        }
#pragma unroll
        for (int q = 0; q < 6; q++) {
            float4 w = make_float4(rW[4 * q], rW[4 * q + 1], rW[4 * q + 2], rW[4 * q + 3]);
            a0 = dot4(w, vv0[11 + q], a0);
            a1 = dot4(w, vv1[11 + q], a1);
        }
        ((float2*)gst)[j * 2 + half] = make_float2(a0, a1);
        __syncthreads();

        // ---- phase B: combine halves, activations, h/x staging ----
        if (t < 256) {
            int d = t & 127, b = t >> 7;
            float4 qi = ((const float4*)gst)[d];
            float4 qf = ((const float4*)gst)[128 + d];
            float4 qg = ((const float4*)gst)[256 + d];
            float4 qo = ((const float4*)gst)[384 + d];
            float gi = b ? (qi.y + qi.w) : (qi.x + qi.z);
            float gf = b ? (qf.y + qf.w) : (qf.x + qf.z);
            float gg = b ? (qg.y + qg.w) : (qg.x + qg.z);
            float go = b ? (qo.y + qo.w) : (qo.x + qo.z);
            c = sigf(gf) * c + sigf(gi) * tanh_(gg);
            float h = sigf(go) * tanh_(c);
            vec[b * VSTR + 8 + d] = h;
        } else if (t < 272) {
            int u = t - 256, b = u >> 3, k = u & 7;
            vec[b * VSTR + k] = xr;                    // x_{step+1}
            int nt = step + 2;
            if (nt < 1024)
                xr = g_h1[((long)(b0 + b) * 1024 + nt) * 8 + k];
        }
        __syncthreads();
    }

    // ---- epilogue: out[b] = (h @ W1^T + b1) @ W2^T + b2 ----
    if (t < 128) {
        int b = t >> 6, jj = t & 63;
        const float4* hv4 = (const float4*)(vec + b * VSTR + 8);
        const float4* w1  = (const float4*)(W1 + jj * 128);
        float m = b1[jj];
#pragma unroll
        for (int q = 0; q < 32; q++) m = dot4(w1[q], hv4[q], m);
        float p = m * W2[jj];
#pragma unroll
        for (int off = 16; off; off >>= 1)
            p += __shfl_xor_sync(0xffffffff, p, off);
        if ((t & 31) == 0) red[t >> 5] = p;
    }
    __syncthreads();
    if (t < 2)
        out[b0 + t] = red[t * 2] + red[t * 2 + 1] + b2[0];
}

// =================================================================
extern "C" void kernel_launch(void* const* d_in, const int* in_sizes, int n_in,
                              void* d_out, int out_size) {
    const float* x     = (const float*)d_in[0];
    // d_in[1] = data (unused)
    const float* W_ih1 = (const float*)d_in[2];
    const float* W_hh1 = (const float*)d_in[3];
    const float* b_ih1 = (const float*)d_in[4];
    const float* b_hh1 = (const float*)d_in[5];
    const float* W_ih2 = (const float*)d_in[6];
    const float* W_hh2 = (const float*)d_in[7];
    const float* b_ih2 = (const float*)d_in[8];
    const float* b_hh2 = (const float*)d_in[9];
    const float* W1    = (const float*)d_in[10];
    const float* b1    = (const float*)d_in[11];
    const float* W2    = (const float*)d_in[12];
    const float* b2    = (const float*)d_in[13];
    float* out = (float*)d_out;

    lstm1_kernel<<<1024, 256>>>(x, W_ih1, W_hh1, b_ih1, b_hh1);

    cudaFuncSetAttribute(lstm2_kernel,
                         cudaFuncAttributeMaxDynamicSharedMemorySize, SM_BYTES);
    lstm2_kernel<<<128, 1024, SM_BYTES>>>(W_ih2, W_hh2, b_ih2, b_hh2,
                                          W1, b1, W2, b2, out);
}

// round 4
// speedup vs baseline: 1.2131x; 1.1979x over previous
#include <cuda_runtime.h>
#include <cuda_fp16.h>

// ---------------- scratch (no cudaMalloc allowed) ----------------
__device__ float g_h1[256 * 1024 * 8];   // LSTM1 outputs, [B][S][8], 8MB

// ---------------- fast activations ----------------
__device__ __forceinline__ float fast_rcp(float x) {
    float r; asm("rcp.approx.ftz.f32 %0, %1;" : "=f"(r) : "f"(x)); return r;
}
__device__ __forceinline__ float fast_ex2(float x) {
    float r; asm("ex2.approx.ftz.f32 %0, %1;" : "=f"(r) : "f"(x)); return r;
}
__device__ __forceinline__ float sigf(float x) {
    return fast_rcp(1.0f + fast_ex2(-1.4426950408889634f * x));
}
__device__ __forceinline__ float tanh_(float x) {
    return fmaf(2.0f, sigf(2.0f * x), -1.0f);
}
__device__ __forceinline__ float dot4(float4 w, float4 v, float a) {
    a = fmaf(w.x, v.x, a); a = fmaf(w.y, v.y, a);
    a = fmaf(w.z, v.z, a); a = fmaf(w.w, v.w, a);
    return a;
}
// accumulate 4 k's (two half2 weight regs) for 2 batches into (a0,a1)
__device__ __forceinline__ void acc4(unsigned int wa, unsigned int wb,
                                     float4 v0, float4 v1,
                                     float& a0, float& a1) {
    __half2 ha = *reinterpret_cast<__half2*>(&wa);
    __half2 hb = *reinterpret_cast<__half2*>(&wb);
    float w0 = __low2float(ha),  w1 = __high2float(ha);
    float w2 = __low2float(hb),  w3 = __high2float(hb);
    a0 = fmaf(w0, v0.x, a0); a0 = fmaf(w1, v0.y, a0);
    a0 = fmaf(w2, v0.z, a0); a0 = fmaf(w3, v0.w, a0);
    a1 = fmaf(w0, v1.x, a1); a1 = fmaf(w1, v1.y, a1);
    a1 = fmaf(w2, v1.z, a1); a1 = fmaf(w3, v1.w, a1);
}

// =================================================================
// Kernel 1: LSTM1. One thread per (b,s) sequence: 16 steps, input=1, H=8.
// =================================================================
__global__ __launch_bounds__(256) void lstm1_kernel(
    const float* __restrict__ x,
    const float* __restrict__ W_ih1, const float* __restrict__ W_hh1,
    const float* __restrict__ b_ih1, const float* __restrict__ b_hh1)
{
    __shared__ float sw_ih[32];
    __shared__ float sw_hh[32][8];
    __shared__ float sbias[32];
    int tid = threadIdx.x;
    if (tid < 32) { sw_ih[tid] = W_ih1[tid]; sbias[tid] = b_ih1[tid] + b_hh1[tid]; }
    if (tid < 256) sw_hh[tid >> 3][tid & 7] = W_hh1[tid];
    __syncthreads();

    long n = (long)blockIdx.x * 256 + tid;
    const float4* xp = (const float4*)(x + n * 16);
    float4 xq[4];
    xq[0] = xp[0]; xq[1] = xp[1]; xq[2] = xp[2]; xq[3] = xp[3];
    float xv[16];
#pragma unroll
    for (int i = 0; i < 4; i++) {
        xv[4 * i + 0] = xq[i].x; xv[4 * i + 1] = xq[i].y;
        xv[4 * i + 2] = xq[i].z; xv[4 * i + 3] = xq[i].w;
    }

    float h[8], c[8];
#pragma unroll
    for (int d = 0; d < 8; d++) { h[d] = 0.f; c[d] = 0.f; }

#pragma unroll
    for (int t = 0; t < 16; t++) {
        float xt = xv[t];
        float hn[8];
#pragma unroll
        for (int d = 0; d < 8; d++) {
            float gi = fmaf(sw_ih[d],      xt, sbias[d]);
            float gf = fmaf(sw_ih[8 + d],  xt, sbias[8 + d]);
            float gg = fmaf(sw_ih[16 + d], xt, sbias[16 + d]);
            float go = fmaf(sw_ih[24 + d], xt, sbias[24 + d]);
#pragma unroll
            for (int e = 0; e < 8; e++) {
                float he = h[e];
                gi = fmaf(sw_hh[d][e],      he, gi);
                gf = fmaf(sw_hh[8 + d][e],  he, gf);
                gg = fmaf(sw_hh[16 + d][e], he, gg);
                go = fmaf(sw_hh[24 + d][e], he, go);
            }
            c[d]  = sigf(gf) * c[d] + sigf(gi) * tanh_(gg);
            hn[d] = sigf(go) * tanh_(c[d]);
        }
#pragma unroll
        for (int d = 0; d < 8; d++) h[d] = hn[d];
    }

    float4* o = (float4*)(g_h1 + n * 8);
    o[0] = make_float4(h[0], h[1], h[2], h[3]);
    o[1] = make_float4(h[4], h[5], h[6], h[7]);
}

// =================================================================
// Kernel 2: LSTM2, persistent, 128 CTAs x 1024 threads, 2 batches/CTA.
// Thread t: row-pair p = t & 255 (rows p, p+256), k-quarter kq = t >> 8.
//   K windows (in the 136-length gate row: k<8 -> W_ih, else W_hh col k-8):
//     kq 0..2: k in [36kq, 36kq+36): 32 in smem fp16, last 4 in fp32 regs
//     kq 3:    k in [108, 136):      24 in smem fp16, last 4 in fp32 regs
//   fp16 weights: slot (kq*256+p), stride 144 B (9x16: conflict-free LDS.128);
//     row0 halves at [0,64), row1 at [64,128).
// vec[b][144]: [0..8) = x_t, [8..136) = h (fp32, broadcast reads).
// Gate partials: gst2[kq][b][p] = float2(acc_row_p, acc_row_{p+256}).
//   Pair p<128 = (i_d, g_d); pair 128+d = (f_d, o_d) -> phase B reads LDS.64.
// =================================================================
#define VSTR 144
#define WSLOT 144                                   // bytes per weight slot
#define OFF_W   0                                   // 1024*144 = 147456 B
#define OFF_VEC (1024 * WSLOT)                      // 2*144*4 = 1152 B
#define OFF_GST (OFF_VEC + 2 * VSTR * 4)            // 4*2*256*8 = 16384 B
#define OFF_RED (OFF_GST + 16384)                   // 32 B
#define SM_BYTES (OFF_RED + 32)

__global__ void __launch_bounds__(1024, 1) lstm2_kernel(
    const float* __restrict__ W_ih2, const float* __restrict__ W_hh2,
    const float* __restrict__ b_ih2, const float* __restrict__ b_hh2,
    const float* __restrict__ W1, const float* __restrict__ b1,
    const float* __restrict__ W2, const float* __restrict__ b2,
    float* __restrict__ out)
{
    extern __shared__ char sm[];
    char*   smW = sm + OFF_W;
    float*  vec = (float*)(sm + OFF_VEC);
    float2* g2  = (float2*)(sm + OFF_GST);
    float*  red = (float*)(sm + OFF_RED);

    const int t  = threadIdx.x;
    const int p  = t & 255;                // row pair: rows p, p+256
    const int kq = t >> 8;                 // k-quarter
    const int b0 = blockIdx.x * 2;

    const int  kb  = 36 * kq;              // window start
    const bool big = (kq < 3);
    const int  nh2 = big ? 16 : 12;        // half2 count per row in smem

    char* wslot = smW + (kq * 256 + p) * WSLOT;

    // ---- fill fp16 weight slot (once) ----
#pragma unroll
    for (int r = 0; r < 2; r++) {
        int row = p + 256 * r;
        unsigned int* dst = (unsigned int*)(wslot + r * 64);
        for (int m = 0; m < nh2; m++) {
            int k = kb + 2 * m;
            float f0 = (k < 8)     ? W_ih2[row * 8 + k]     : W_hh2[row * 128 + k - 8];
            float f1 = (k + 1 < 8) ? W_ih2[row * 8 + k + 1] : W_hh2[row * 128 + k - 7];
            __half2 hh = __floats2half2_rn(f0, f1);
            dst[m] = *reinterpret_cast<unsigned int*>(&hh);
        }
    }
    // ---- fp32 register tail: 1 float4 per row (hh cols kb+24 or 124) ----
    const int hhc = big ? (kb + 24) : 124;
    float4 rw0 = *(const float4*)(W_hh2 + p * 128 + hhc);
    float4 rw1 = *(const float4*)(W_hh2 + (p + 256) * 128 + hhc);

    float bias0 = 0.f, bias1 = 0.f;
    if (kq == 0) {
        bias0 = b_ih2[p] + b_hh2[p];
        bias1 = b_ih2[p + 256] + b_hh2[p + 256];
    }

    // ---- init vec (h=0) and stage x_0 ----
    if (t < 2 * VSTR) vec[t] = 0.f;
    __syncthreads();
    if (t < 16) {
        int b = t >> 3, k = t & 7;
        vec[b * VSTR + k] = g_h1[((long)(b0 + b) * 1024 + 0) * 8 + k];
    }
    float c = 0.f;     // cell state (threads t<256: d = t&127, b = t>>7)
    float xr = 0.f;    // x prefetch register (threads 256..271)
    if (t >= 256 && t < 272) {
        int u = t - 256, b = u >> 3, k = u & 7;
        xr = g_h1[((long)(b0 + b) * 1024 + 1) * 8 + k];
    }
    __syncthreads();

    const float4* V0 = (const float4*)(vec);
    const float4* V1 = (const float4*)(vec + VSTR);
    const uint4*  Wr0 = (const uint4*)(wslot);
    const uint4*  Wr1 = (const uint4*)(wslot + 64);
    const int qb = 9 * kq;                     // vec float4 base of window
    float2* gout0 = g2 + (kq * 2 + 0) * 256 + p;
    float2* gout1 = g2 + (kq * 2 + 1) * 256 + p;

    for (int step = 0; step < 1024; step++) {
        // ---- phase A: partial gate sums, 2 rows x 2 batches ----
        float a00 = bias0, a01 = bias0;        // row p, batches 0/1
        float a10 = bias1, a11 = bias1;        // row p+256
        if (big) {
            uint4 A0 = Wr0[0], A1 = Wr0[1], A2 = Wr0[2], A3 = Wr0[3];
            uint4 B0 = Wr1[0], B1 = Wr1[1], B2 = Wr1[2], B3 = Wr1[3];
            float4 v0, v1;
            v0 = V0[qb + 0]; v1 = V1[qb + 0];
            acc4(A0.x, A0.y, v0, v1, a00, a01); acc4(B0.x, B0.y, v0, v1, a10, a11);
            v0 = V0[qb + 1]; v1 = V1[qb + 1];
            acc4(A0.z, A0.w, v0, v1, a00, a01); acc4(B0.z, B0.w, v0, v1, a10, a11);
            v0 = V0[qb + 2]; v1 = V1[qb + 2];
            acc4(A1.x, A1.y, v0, v1, a00, a01); acc4(B1.x, B1.y, v0, v1, a10, a11);
            v0 = V0[qb + 3]; v1 = V1[qb + 3];
            acc4(A1.z, A1.w, v0, v1, a00, a01); acc4(B1.z, B1.w, v0, v1, a10, a11);
            v0 = V0[qb + 4]; v1 = V1[qb + 4];
            acc4(A2.x, A2.y, v0, v1, a00, a01); acc4(B2.x, B2.y, v0, v1, a10, a11);
            v0 = V0[qb + 5]; v1 = V1[qb + 5];
            acc4(A2.z, A2.w, v0, v1, a00, a01); acc4(B2.z, B2.w, v0, v1, a10, a11);
            v0 = V0[qb + 6]; v1 = V1[qb + 6];
            acc4(A3.x, A3.y, v0, v1, a00, a01); acc4(B3.x, B3.y, v0, v1, a10, a11);
            v0 = V0[qb + 7]; v1 = V1[qb + 7];
            acc4(A3.z, A3.w, v0, v1, a00, a01); acc4(B3.z, B3.w, v0, v1, a10, a11);
            v0 = V0[qb + 8]; v1 = V1[qb + 8];
            a00 = dot4(rw0, v0, a00); a01 = dot4(rw0, v1, a01);
            a10 = dot4(rw1, v0, a10); a11 = dot4(rw1, v1, a11);
        } else {
            uint4 A0 = Wr0[0], A1 = Wr0[1], A2 = Wr0[2];
            uint4 B0 = Wr1[0], B1 = Wr1[1], B2 = Wr1[2];
            float4 v0, v1;
            v0 = V0[27]; v1 = V1[27];
            acc4(A0.x, A0.y, v0, v1, a00, a01); acc4(B0.x, B0.y, v0, v1, a10, a11);
            v0 = V0[28]; v1 = V1[28];
            acc4(A0.z, A0.w, v0, v1, a00, a01); acc4(B0.z, B0.w, v0, v1, a10, a11);
            v0 = V0[29]; v1 = V1[29];
            acc4(A1.x, A1.y, v0, v1, a00, a01); acc4(B1.x, B1.y, v0, v1, a10, a11);
            v0 = V0[30]; v1 = V1[30];
            acc4(A1.z, A1.w, v0, v1, a00, a01); acc4(B1.z, B1.w, v0, v1, a10, a11);
            v0 = V0[31]; v1 = V1[31];
            acc4(A2.x, A2.y, v0, v1, a00, a01); acc4(B2.x, B2.y, v0, v1, a10, a11);
            v0 = V0[32]; v1 = V1[32];
            acc4(A2.z, A2.w, v0, v1, a00, a01); acc4(B2.z, B2.w, v0, v1, a10, a11);
            v0 = V0[33]; v1 = V1[33];
            a00 = dot4(rw0, v0, a00); a01 = dot4(rw0, v1, a01);
            a10 = dot4(rw1, v0, a10); a11 = dot4(rw1, v1, a11);
        }
        *gout0 = make_float2(a00, a10);
        *gout1 = make_float2(a01, a11);
        __syncthreads();

        // ---- phase B: combine quarters, activations, h/x staging ----
        if (t < 256) {
            int d = t & 127, b = t >> 7;
            const float2* gb = g2 + b * 256;
            float2 ig0 = gb[0 * 512 + d],       fo0 = gb[0 * 512 + 128 + d];
            float2 ig1 = gb[2 * 256 + d],       fo1 = gb[2 * 256 + 128 + d];
            float2 ig2 = gb[4 * 256 + d],       fo2 = gb[4 * 256 + 128 + d];
            float2 ig3 = gb[6 * 256 + d],       fo3 = gb[6 * 256 + 128 + d];
            float gi = (ig0.x + ig1.x) + (ig2.x + ig3.x);
            float gg = (ig0.y + ig1.y) + (ig2.y + ig3.y);
            float gf = (fo0.x + fo1.x) + (fo2.x + fo3.x);
            float go = (fo0.y + fo1.y) + (fo2.y + fo3.y);
            c = sigf(gf) * c + sigf(gi) * tanh_(gg);
            float h = sigf(go) * tanh_(c);
            vec[b * VSTR + 8 + d] = h;
        } else if (t < 272) {
            int u = t - 256, b = u >> 3, k = u & 7;
            vec[b * VSTR + k] = xr;                    // x_{step+1}
            int nt = step + 2;
            if (nt < 1024)
                xr = g_h1[((long)(b0 + b) * 1024 + nt) * 8 + k];
        }
        __syncthreads();
    }

    // ---- epilogue: out[b] = (h @ W1^T + b1) @ W2^T + b2 ----
    if (t < 128) {
        int b = t >> 6, jj = t & 63;
        const float4* hv4 = (const float4*)(vec + b * VSTR + 8);
        const float4* w1  = (const float4*)(W1 + jj * 128);
        float m = b1[jj];
#pragma unroll
        for (int q = 0; q < 32; q++) m = dot4(w1[q], hv4[q], m);
        float pr = m * W2[jj];
#pragma unroll
        for (int off = 16; off; off >>= 1)
            pr += __shfl_xor_sync(0xffffffff, pr, off);
        if ((t & 31) == 0) red[t >> 5] = pr;
    }
    __syncthreads();
    if (t < 2)
        out[b0 + t] = red[t * 2] + red[t * 2 + 1] + b2[0];
}

// =================================================================
extern "C" void kernel_launch(void* const* d_in, const int* in_sizes, int n_in,
                              void* d_out, int out_size) {
    const float* x     = (const float*)d_in[0];
    // d_in[1] = data (unused)
    const float* W_ih1 = (const float*)d_in[2];
    const float* W_hh1 = (const float*)d_in[3];
    const float* b_ih1 = (const float*)d_in[4];
    const float* b_hh1 = (const float*)d_in[5];
    const float* W_ih2 = (const float*)d_in[6];
    const float* W_hh2 = (const float*)d_in[7];
    const float* b_ih2 = (const float*)d_in[8];
    const float* b_hh2 = (const float*)d_in[9];
    const float* W1    = (const float*)d_in[10];
    const float* b1    = (const float*)d_in[11];
    const float* W2    = (const float*)d_in[12];
    const float* b2    = (const float*)d_in[13];
    float* out = (float*)d_out;

    lstm1_kernel<<<1024, 256>>>(x, W_ih1, W_hh1, b_ih1, b_hh1);

    cudaFuncSetAttribute(lstm2_kernel,
                         cudaFuncAttributeMaxDynamicSharedMemorySize, SM_BYTES);
    lstm2_kernel<<<128, 1024, SM_BYTES>>>(W_ih2, W_hh2, b_ih2, b_hh2,
                                          W1, b1, W2, b2, out);
}